// round 1
// baseline (speedup 1.0000x reference)
#include <cuda_runtime.h>

// ---------------------------------------------------------------------------
// PreActBlock_conv_Q  (DoReFa 4-bit quantized pre-act block)
//
// Exact-integer formulation:
//   act  a = j/15,                j in [0,15]
//   wq   w = Mw*(2q-15)/15,       q in [0,15]  -> store qi = 2q-15 in int8
//   conv y = (Mw/225) * S,        S = sum j*qi  (|S| <= 518400, exact int32)
// BN1 stats computed exactly from int64 sums of S.
// ---------------------------------------------------------------------------

#define NELEM   12845056        // 16*256*56*56
#define M_TOT   50176           // 16*56*56
#define CCH     256
#define HWSZ    3136
#define HH_     56
#define WW_     56
#define KW_ELEMS 589824         // 256*256*9
#define KG      576             // int32 k-groups per cout (2304 bytes / 4)

// ----- scratch (device globals; no allocation allowed) -----
__device__ int       g_a0[NELEM / 4];      // act0 int8, NHWC (c innermost)
__device__ int       g_a1[NELEM / 4];      // act1 int8, NHWC
__device__ int       g_y0[NELEM];          // conv0 integer output S, [m][cout]
__device__ int       g_wq0[KW_ELEMS / 4];  // int8 weights [cout][r*256+cin]
__device__ int       g_wq1[KW_ELEMS / 4];
__device__ int       g_wmaxbits[2];
__device__ float     g_mean0[CCH], g_rstd0[CCH];
__device__ long long g_sum1[CCH], g_sumsq1[CCH];
__device__ float     g_mean1[CCH], g_rstd1[CCH];

// ---------------------------------------------------------------------------
__global__ void init_kernel() {
    int t = threadIdx.x;
    if (t < 2) g_wmaxbits[t] = 0;
    g_sum1[t] = 0;
    g_sumsq1[t] = 0;
}

// max |tanh(w)| -> g_wmaxbits[slot] (positive floats compare as ints)
__global__ void wabsmax_kernel(const float* __restrict__ w, int slot) {
    int i = blockIdx.x * blockDim.x + threadIdx.x;
    float m = 0.0f;
    for (; i < KW_ELEMS; i += gridDim.x * blockDim.x)
        m = fmaxf(m, fabsf(tanhf(w[i])));
#pragma unroll
    for (int o = 16; o; o >>= 1)
        m = fmaxf(m, __shfl_xor_sync(0xFFFFFFFFu, m, o));
    if ((threadIdx.x & 31) == 0)
        atomicMax(&g_wmaxbits[slot], __float_as_int(m));
}

// quantize weights: OIHW fp32 -> [cout][r*256+cin] int8 (value 2q-15)
__global__ void wquant_kernel(const float* __restrict__ w, int slot) {
    int idx = blockIdx.x * 256 + threadIdx.x;
    if (idx >= KW_ELEMS) return;
    float M = __int_as_float(g_wmaxbits[slot]);
    float t = tanhf(w[idx]);
    float wn = __fdiv_rn(t, 2.0f * M) + 0.5f;
    int q = __float2int_rn(wn * 15.0f);
    int qi = 2 * q - 15;
    int cout = idx / 2304;
    int rem  = idx - cout * 2304;
    int cin  = rem / 9;
    int r    = rem - cin * 9;
    signed char* dst = (signed char*)(slot == 0 ? g_wq0 : g_wq1);
    dst[cout * 2304 + r * 256 + cin] = (signed char)qi;
}

// per-channel mean / rstd of x (NCHW), double accumulation
__global__ void bn0_stats_kernel(const float* __restrict__ x) {
    int c = blockIdx.x;
    double s = 0.0, ss = 0.0;
    for (int n = 0; n < 16; n++) {
        const float* p = x + ((size_t)(n * CCH + c)) * HWSZ;
        for (int i = threadIdx.x; i < HWSZ; i += blockDim.x) {
            float v = p[i];
            s += v;
            ss += (double)v * v;
        }
    }
    __shared__ double sh[256], sh2[256];
    sh[threadIdx.x] = s; sh2[threadIdx.x] = ss;
    __syncthreads();
    for (int o = 128; o; o >>= 1) {
        if (threadIdx.x < o) {
            sh[threadIdx.x]  += sh[threadIdx.x + o];
            sh2[threadIdx.x] += sh2[threadIdx.x + o];
        }
        __syncthreads();
    }
    if (threadIdx.x == 0) {
        double mean = sh[0] / (double)M_TOT;
        double var  = sh2[0] / (double)M_TOT - mean * mean;
        g_mean0[c] = (float)mean;
        g_rstd0[c] = (float)(1.0 / sqrt(var + 1e-5));
    }
}

// BN0 + relu + clip + quant + NCHW->NHWC transpose -> g_a0 (int8)
__global__ void act0_kernel(const float* __restrict__ x,
                            const float* __restrict__ gamma,
                            const float* __restrict__ beta) {
    __shared__ signed char tile[32][33];
    int n   = blockIdx.z;
    int c0  = blockIdx.y * 32;
    int hw0 = blockIdx.x * 32;
    int tx = threadIdx.x, ty = threadIdx.y;
#pragma unroll
    for (int i = 0; i < 4; i++) {
        int c = c0 + ty + 8 * i;
        float v  = x[((size_t)(n * CCH + c)) * HWSZ + hw0 + tx];
        float xn = (v - g_mean0[c]) * g_rstd0[c] * gamma[c] + beta[c];
        float r  = fminf(fmaxf(xn, 0.0f), 1.0f);
        tile[ty + 8 * i][tx] = (signed char)__float2int_rn(r * 15.0f);
    }
    __syncthreads();
    signed char* a0 = (signed char*)g_a0;
#pragma unroll
    for (int i = 0; i < 4; i++) {
        int hw = hw0 + ty + 8 * i;
        a0[((size_t)(n * HWSZ + hw)) * CCH + c0 + tx] = tile[tx][ty + 8 * i];
    }
}

// ---------------------------------------------------------------------------
// int8 implicit-GEMM 3x3 conv:  C[m][cout] = sum_k A[m][k] * W[cout][k]
// M = 50176, N = 256, K = 2304 (r-major, cin inner).
// Tile: 128 x 128 x 64B, 256 threads, 8x8 register tile, dp4a.
// epi==0: store int S into g_y0.  epi==1: out = S*Mw1/225 + shortcut (NCHW).
// ---------------------------------------------------------------------------
__global__ void __launch_bounds__(256, 2) conv_gemm_kernel(
    float* __restrict__ Out, const float* __restrict__ Xin, int epi)
{
    __shared__ int As[16 * 132];   // [kk][mm], row stride 132 ints (16B-aligned)
    __shared__ int Bs[16 * 132];   // [kk][nn]

    const int* __restrict__ A  = (epi == 0) ? g_a0  : g_a1;
    const int* __restrict__ Bw = (epi == 0) ? g_wq0 : g_wq1;

    const int tid = threadIdx.x;
    const int tx = tid & 15, ty = tid >> 4;
    const int mBase = blockIdx.x * 128;   // 392 blocks
    const int nBase = blockIdx.y * 128;   // 2 blocks

    int acc[8][8];
#pragma unroll
    for (int i = 0; i < 8; i++)
#pragma unroll
        for (int j = 0; j < 8; j++) acc[i][j] = 0;

    int nb[8], h0[8], w0[8];
#pragma unroll
    for (int i = 0; i < 8; i++) {
        int m  = mBase + ty + 16 * i;
        int n  = m / HWSZ;
        int hw = m - n * HWSZ;
        nb[i] = n * HWSZ;
        h0[i] = hw / WW_;
        w0[i] = hw - h0[i] * WW_;
    }

    for (int kt = 0; kt < 36; kt++) {
        int r  = kt >> 2;
        int dh = r / 3 - 1;
        int dw = r - (r / 3) * 3 - 1;
        int cinb = (kt & 3) << 4;
#pragma unroll
        for (int i = 0; i < 8; i++) {
            int hh = h0[i] + dh, ww = w0[i] + dw;
            int v = 0;
            if ((unsigned)hh < HH_ && (unsigned)ww < WW_)
                v = A[((size_t)(nb[i] + hh * WW_ + ww)) * 64 + cinb + tx];
            As[tx * 132 + ty + 16 * i] = v;
        }
#pragma unroll
        for (int i = 0; i < 8; i++)
            Bs[tx * 132 + ty + 16 * i] =
                Bw[(size_t)(nBase + ty + 16 * i) * KG + kt * 16 + tx];
        __syncthreads();

        const int4* As4 = (const int4*)As;
        const int4* Bs4 = (const int4*)Bs;
#pragma unroll
        for (int kk = 0; kk < 16; kk++) {
            int4 pa0 = As4[kk * 33 + ty * 2];
            int4 pa1 = As4[kk * 33 + ty * 2 + 1];
            int4 pb0 = Bs4[kk * 33 + tx * 2];
            int4 pb1 = Bs4[kk * 33 + tx * 2 + 1];
            int av[8] = {pa0.x, pa0.y, pa0.z, pa0.w, pa1.x, pa1.y, pa1.z, pa1.w};
            int bv[8] = {pb0.x, pb0.y, pb0.z, pb0.w, pb1.x, pb1.y, pb1.z, pb1.w};
#pragma unroll
            for (int i = 0; i < 8; i++)
#pragma unroll
                for (int j = 0; j < 8; j++)
                    acc[i][j] = __dp4a(av[i], bv[j], acc[i][j]);
        }
        __syncthreads();
    }

    if (epi == 0) {
#pragma unroll
        for (int i = 0; i < 8; i++) {
            int m = mBase + ty * 8 + i;
#pragma unroll
            for (int j = 0; j < 8; j++)
                g_y0[(size_t)m * CCH + nBase + tx * 8 + j] = acc[i][j];
        }
    } else {
        float ys = __int_as_float(g_wmaxbits[1]) * (1.0f / 225.0f);
#pragma unroll
        for (int i = 0; i < 8; i++) {
            int m  = mBase + ty * 8 + i;
            int n  = m / HWSZ;
            int hw = m - n * HWSZ;
#pragma unroll
            for (int j = 0; j < 8; j++) {
                int cout = nBase + tx * 8 + j;
                size_t o = ((size_t)(n * CCH + cout)) * HWSZ + hw;
                Out[o] = (float)acc[i][j] * ys + Xin[o];
            }
        }
    }
}

// exact int64 per-channel sums of conv0 integer output
__global__ void bn1_stats_kernel() {
    int c  = threadIdx.x;            // 256 threads = 256 channels
    int mb = blockIdx.x;             // 256 blocks * 196 rows
    long long s = 0, ss = 0;
    for (int m = mb * 196; m < (mb + 1) * 196; m++) {
        int v = g_y0[(size_t)m * CCH + c];
        s  += v;
        ss += (long long)v * v;
    }
    atomicAdd((unsigned long long*)&g_sum1[c],   (unsigned long long)s);
    atomicAdd((unsigned long long*)&g_sumsq1[c], (unsigned long long)ss);
}

__global__ void bn1_final_kernel() {
    int c = threadIdx.x;
    double ys   = (double)__int_as_float(g_wmaxbits[0]) / 225.0;
    double mean = ys * (double)g_sum1[c] / (double)M_TOT;
    double e2   = ys * ys * (double)g_sumsq1[c] / (double)M_TOT;
    double var  = e2 - mean * mean;
    g_mean1[c] = (float)mean;
    g_rstd1[c] = (float)(1.0 / sqrt(var + 1e-5));
}

// BN1 + relu + clip + quant (same NHWC layout, pure elementwise)
__global__ void act1_kernel(const float* __restrict__ g1,
                            const float* __restrict__ b1) {
    int idx = blockIdx.x * 256 + threadIdx.x;
    int c = idx & 255;
    float ys = __int_as_float(g_wmaxbits[0]) * (1.0f / 225.0f);
    float y  = (float)g_y0[idx] * ys;
    float xn = (y - g_mean1[c]) * g_rstd1[c] * g1[c] + b1[c];
    float r  = fminf(fmaxf(xn, 0.0f), 1.0f);
    ((signed char*)g_a1)[idx] = (signed char)__float2int_rn(r * 15.0f);
}

// ---------------------------------------------------------------------------
extern "C" void kernel_launch(void* const* d_in, const int* in_sizes, int n_in,
                              void* d_out, int out_size) {
    const float* x  = (const float*)d_in[0];
    const float* g0 = (const float*)d_in[1];
    const float* b0 = (const float*)d_in[2];
    const float* w0 = (const float*)d_in[3];
    const float* g1 = (const float*)d_in[4];
    const float* b1 = (const float*)d_in[5];
    const float* w1 = (const float*)d_in[6];
    float* out = (float*)d_out;

    init_kernel<<<1, 256>>>();
    wabsmax_kernel<<<256, 256>>>(w0, 0);
    wabsmax_kernel<<<256, 256>>>(w1, 1);
    wquant_kernel<<<(KW_ELEMS + 255) / 256, 256>>>(w0, 0);
    wquant_kernel<<<(KW_ELEMS + 255) / 256, 256>>>(w1, 1);
    bn0_stats_kernel<<<256, 256>>>(x);
    act0_kernel<<<dim3(98, 8, 16), dim3(32, 8)>>>(x, g0, b0);
    conv_gemm_kernel<<<dim3(392, 2), 256>>>(nullptr, nullptr, 0);
    bn1_stats_kernel<<<256, 256>>>();
    bn1_final_kernel<<<1, 256>>>();
    act1_kernel<<<NELEM / 256, 256>>>(g1, b1);
    conv_gemm_kernel<<<dim3(392, 2), 256>>>(out, x, 1);
}

// round 3
// speedup vs baseline: 2.9714x; 2.9714x over previous
#include <cuda_runtime.h>
#include <cstdint>

// ---------------------------------------------------------------------------
// PreActBlock_conv_Q — exact-integer formulation on legacy IMMA tensor cores
// (mma.sync m16n8k32 s8 — baseline compute_100; tcgen05/TMA need sm_100a
//  which this build's PTX target forbids).
//   act  a = j/15 (store j in int8, 0..15)
//   wq   w = Mw*(2q-15)/15 (store 2q-15 in int8)
//   conv y = (Mw/225) * S,  S exact int32 from IMMA.
// Activations: padded NHWC int8 [16][58][58][256] + 64 guard rows each side
// so the implicit-im2col GEMM needs no bounds checks anywhere.
// ---------------------------------------------------------------------------

#define CCH     256
#define HWSZ    3136
#define PW      58
#define PSP     3364
#define MPAD    53824           // 16*3364
#define MTILES  421
#define MROWS   53888           // 421*128
#define GUARD   64
#define KW_ELEMS 589824
#define CHUNKS  18              // K = 18 * 128 bytes

__device__ signed char g_a0[(MPAD + 2 * GUARD) * CCH];
__device__ signed char g_a1[(MPAD + 2 * GUARD) * CCH];
__device__ int         g_y0[(size_t)MROWS * CCH];
__device__ signed char g_wq0[KW_ELEMS];
__device__ signed char g_wq1[KW_ELEMS];
__device__ int         g_wmaxbits[2];
__device__ float       g_mean0[CCH], g_rstd0[CCH];
__device__ long long   g_sum1[CCH], g_sumsq1[CCH];
__device__ float       g_mean1[CCH], g_rstd1[CCH];

// ---------------------------------------------------------------------------
__device__ __forceinline__ uint32_t smem_u32(const void* p) {
    uint32_t a;
    asm("{ .reg .u64 t; cvta.to.shared.u64 t, %1; cvt.u32.u64 %0, t; }"
        : "=r"(a) : "l"(p));
    return a;
}
__device__ __forceinline__ void cp16(uint32_t dst, const void* src) {
    asm volatile("cp.async.cg.shared.global [%0], [%1], 16;"
                 :: "r"(dst), "l"(src) : "memory");
}
__device__ __forceinline__ void ldx4(uint32_t* r, uint32_t addr) {
    asm volatile("ldmatrix.sync.aligned.m8n8.x4.shared.b16 {%0,%1,%2,%3}, [%4];"
                 : "=r"(r[0]), "=r"(r[1]), "=r"(r[2]), "=r"(r[3]) : "r"(addr));
}
__device__ __forceinline__ void imma(int* d, const uint32_t* a, uint32_t b0, uint32_t b1) {
    asm volatile(
        "mma.sync.aligned.m16n8k32.row.col.s32.s8.s8.s32 "
        "{%0,%1,%2,%3}, {%4,%5,%6,%7}, {%8,%9}, {%0,%1,%2,%3};"
        : "+r"(d[0]), "+r"(d[1]), "+r"(d[2]), "+r"(d[3])
        : "r"(a[0]), "r"(a[1]), "r"(a[2]), "r"(a[3]), "r"(b0), "r"(b1));
}

// ---------------------------------------------------------------------------
__global__ void init_kernel() {
    int t = threadIdx.x;
    if (t < 2) g_wmaxbits[t] = 0;
    g_sum1[t] = 0; g_sumsq1[t] = 0;
}

__global__ void wabsmax_kernel(const float* __restrict__ w, int slot) {
    int i = blockIdx.x * blockDim.x + threadIdx.x;
    float m = 0.0f;
    for (; i < KW_ELEMS; i += gridDim.x * blockDim.x)
        m = fmaxf(m, fabsf(tanhf(w[i])));
#pragma unroll
    for (int o = 16; o; o >>= 1) m = fmaxf(m, __shfl_xor_sync(~0u, m, o));
    if ((threadIdx.x & 31) == 0) atomicMax(&g_wmaxbits[slot], __float_as_int(m));
}

// OIHW fp32 -> [cout][r*256+cin] int8 (value 2q-15)
__global__ void wquant_kernel(const float* __restrict__ w, int slot) {
    int idx = blockIdx.x * 256 + threadIdx.x;
    if (idx >= KW_ELEMS) return;
    float M = __int_as_float(g_wmaxbits[slot]);
    float t = tanhf(w[idx]);
    float wn = __fdiv_rn(t, 2.0f * M) + 0.5f;
    int q = __float2int_rn(wn * 15.0f);
    int cout = idx / 2304;
    int rem  = idx - cout * 2304;
    int cin  = rem / 9;
    int r    = rem - cin * 9;
    (slot == 0 ? g_wq0 : g_wq1)[cout * 2304 + r * 256 + cin] = (signed char)(2 * q - 15);
}

__global__ void bn0_stats_kernel(const float* __restrict__ x) {
    int c = blockIdx.x;
    double s = 0.0, ss = 0.0;
    for (int n = 0; n < 16; n++) {
        const float* p = x + ((size_t)(n * CCH + c)) * HWSZ;
        for (int i = threadIdx.x; i < HWSZ; i += blockDim.x) {
            float v = p[i]; s += v; ss += (double)v * v;
        }
    }
    __shared__ double sh[256], sh2[256];
    sh[threadIdx.x] = s; sh2[threadIdx.x] = ss;
    __syncthreads();
    for (int o = 128; o; o >>= 1) {
        if (threadIdx.x < o) { sh[threadIdx.x] += sh[threadIdx.x+o]; sh2[threadIdx.x] += sh2[threadIdx.x+o]; }
        __syncthreads();
    }
    if (threadIdx.x == 0) {
        double mean = sh[0] / 50176.0;
        double var  = sh2[0] / 50176.0 - mean * mean;
        g_mean0[c] = (float)mean;
        g_rstd0[c] = (float)(1.0 / sqrt(var + 1e-5));
    }
}

// BN0+relu+quant, NCHW -> padded NHWC int8
__global__ void act0_kernel(const float* __restrict__ x,
                            const float* __restrict__ gamma,
                            const float* __restrict__ beta) {
    __shared__ signed char tile[32][33];
    int n = blockIdx.z, c0 = blockIdx.y * 32, hw0 = blockIdx.x * 32;
    int tx = threadIdx.x, ty = threadIdx.y;
#pragma unroll
    for (int i = 0; i < 4; i++) {
        int c = c0 + ty + 8 * i;
        float v  = x[((size_t)(n * CCH + c)) * HWSZ + hw0 + tx];
        float xn = (v - g_mean0[c]) * g_rstd0[c] * gamma[c] + beta[c];
        float r  = fminf(fmaxf(xn, 0.0f), 1.0f);
        tile[ty + 8 * i][tx] = (signed char)__float2int_rn(r * 15.0f);
    }
    __syncthreads();
#pragma unroll
    for (int i = 0; i < 4; i++) {
        int hw = hw0 + ty + 8 * i;
        int h = hw / 56, w = hw - h * 56;
        int mrow = n * PSP + (h + 1) * PW + (w + 1);
        g_a0[(size_t)(mrow + GUARD) * CCH + c0 + tx] = tile[tx][ty + 8 * i];
    }
}

__global__ void zero_halo0_kernel() {
    int idx = blockIdx.x * 256 + threadIdx.x;
    int mrow = idx >> 8;
    int rem = mrow % PSP;
    int hp = rem / PW, wp = rem - hp * PW;
    if (!((hp >= 1) && (hp <= 56) && (wp >= 1) && (wp <= 56)))
        g_a0[(size_t)(mrow + GUARD) * CCH + (idx & 255)] = 0;
}

// ---------------------------------------------------------------------------
// IMMA implicit-GEMM conv: CTA tile 128x128, K = 18 chunks x 128B.
// Warp tile 32x64: warp_m = wid&3, warp_n = wid>>2. Smem rows 128B, 16B-chunk
// XOR swizzle (chunk ^ (row&7)) -> conflict-free ldmatrix.x4.
// ---------------------------------------------------------------------------
__global__ void __launch_bounds__(256, 2) conv_imma_kernel(
    const signed char* __restrict__ A,   // guard-offset padded NHWC base
    const signed char* __restrict__ W,   // [256][2304]
    int* __restrict__ Y)                 // [MROWS][256]
{
    extern __shared__ char smem[];
    const uint32_t sb = smem_u32(smem);
    const int tid = threadIdx.x;
    const int lane = tid & 31, wid = tid >> 5;
    const int warp_m = wid & 3, warp_n = wid >> 2;
    const int mbase = blockIdx.x * 128;
    const int nbase = blockIdx.y * 128;

    const int cr = tid >> 1;            // load row 0..127
    const int seg0 = (tid & 1) * 4;     // 4 x 16B segments per thread per tile

    int acc[2][8][4];
#pragma unroll
    for (int mt = 0; mt < 2; mt++)
#pragma unroll
        for (int nt = 0; nt < 8; nt++)
#pragma unroll
            for (int v = 0; v < 4; v++) acc[mt][nt][v] = 0;

    // precompute ldmatrix lane geometry
    int a_row[2], a_sw[2];
#pragma unroll
    for (int mt = 0; mt < 2; mt++) {
        a_row[mt] = warp_m * 32 + mt * 16 + ((lane >> 3) & 1) * 8 + (lane & 7);
        a_sw[mt]  = a_row[mt] & 7;
    }
    const int a_ch = lane >> 4;          // 0/1
    int b_row[4], b_sw[4];
#pragma unroll
    for (int jp = 0; jp < 4; jp++) {
        b_row[jp] = warp_n * 64 + jp * 16 + (lane >> 4) * 8 + (lane & 7);
        b_sw[jp]  = b_row[jp] & 7;
    }
    const int b_ch = (lane >> 3) & 1;

#define LOAD_CHUNK(s, buf) do {                                               \
    int _r = (s) >> 1;                                                        \
    int _off = (_r / 3 - 1) * PW + (_r % 3) - 1;                              \
    int _cinb = ((s) & 1) << 7;                                               \
    const signed char* _sa = A + (size_t)(mbase + _off + cr) * CCH + _cinb;   \
    uint32_t _da = sb + (buf) * 32768u + cr * 128u;                           \
    const signed char* _sw = W + (size_t)(nbase + cr) * 2304 + (s) * 128;     \
    uint32_t _dw = _da + 16384u;                                              \
    _Pragma("unroll")                                                         \
    for (int _i = 0; _i < 4; _i++) {                                          \
        int _seg = seg0 + _i;                                                 \
        cp16(_da + (uint32_t)((_seg ^ (cr & 7)) << 4), _sa + _seg * 16);      \
        cp16(_dw + (uint32_t)((_seg ^ (cr & 7)) << 4), _sw + _seg * 16);      \
    }                                                                         \
    asm volatile("cp.async.commit_group;" ::: "memory");                      \
} while (0)

#define COMPUTE_CHUNK(buf) do {                                               \
    uint32_t _As = sb + (buf) * 32768u;                                       \
    uint32_t _Bs = _As + 16384u;                                              \
    _Pragma("unroll")                                                         \
    for (int kc = 0; kc < 4; kc++) {                                          \
        uint32_t afr[2][4];                                                   \
        _Pragma("unroll")                                                     \
        for (int mt = 0; mt < 2; mt++) {                                      \
            int ch = 2 * kc + a_ch;                                           \
            ldx4(afr[mt], _As + a_row[mt] * 128u +                            \
                          (uint32_t)((ch ^ a_sw[mt]) << 4));                  \
        }                                                                     \
        _Pragma("unroll")                                                     \
        for (int jp = 0; jp < 4; jp++) {                                      \
            uint32_t bfr[4];                                                  \
            int ch = 2 * kc + b_ch;                                           \
            ldx4(bfr, _Bs + b_row[jp] * 128u +                                \
                      (uint32_t)((ch ^ b_sw[jp]) << 4));                      \
            _Pragma("unroll")                                                 \
            for (int mt = 0; mt < 2; mt++) {                                  \
                imma(acc[mt][2 * jp],     afr[mt], bfr[0], bfr[1]);           \
                imma(acc[mt][2 * jp + 1], afr[mt], bfr[2], bfr[3]);           \
            }                                                                 \
        }                                                                     \
    }                                                                         \
} while (0)

    LOAD_CHUNK(0, 0);
    for (int s = 0; s < CHUNKS; s++) {
        if (s + 1 < CHUNKS) {
            LOAD_CHUNK(s + 1, (s + 1) & 1);
            asm volatile("cp.async.wait_group 1;" ::: "memory");
        } else {
            asm volatile("cp.async.wait_group 0;" ::: "memory");
        }
        __syncthreads();
        COMPUTE_CHUNK(s & 1);
        __syncthreads();
    }

    // epilogue: int2 stores (c0,c1) / (c2,c3)
    const int erow = mbase + warp_m * 32 + (lane >> 2);
    const int ecol = nbase + warp_n * 64 + (lane & 3) * 2;
#pragma unroll
    for (int mt = 0; mt < 2; mt++) {
#pragma unroll
        for (int nt = 0; nt < 8; nt++) {
            int r0 = erow + mt * 16;
            int c  = ecol + nt * 8;
            *(int2*)&Y[(size_t)r0 * CCH + c]       = make_int2(acc[mt][nt][0], acc[mt][nt][1]);
            *(int2*)&Y[(size_t)(r0 + 8) * CCH + c] = make_int2(acc[mt][nt][2], acc[mt][nt][3]);
        }
    }
}

// exact int64 per-channel sums of conv0 integer output (valid rows only)
__global__ void bn1_stats_kernel() {
    int c = threadIdx.x;
    long long s = 0, ss = 0;
    for (int v = blockIdx.x * 196; v < (blockIdx.x + 1) * 196; v++) {
        int n = v / HWSZ, hw = v - n * HWSZ;
        int h = hw / 56, w = hw - h * 56;
        int mrow = n * PSP + (h + 1) * PW + (w + 1);
        long long iv = (long long)g_y0[(size_t)mrow * CCH + c];
        s += iv; ss += iv * iv;
    }
    atomicAdd((unsigned long long*)&g_sum1[c],   (unsigned long long)s);
    atomicAdd((unsigned long long*)&g_sumsq1[c], (unsigned long long)ss);
}

__global__ void bn1_final_kernel() {
    int c = threadIdx.x;
    double ys   = (double)__int_as_float(g_wmaxbits[0]) / 225.0;
    double mean = ys * (double)g_sum1[c] / 50176.0;
    double e2   = ys * ys * (double)g_sumsq1[c] / 50176.0;
    g_mean1[c] = (float)mean;
    g_rstd1[c] = (float)(1.0 / sqrt(e2 - mean * mean + 1e-5));
}

// BN1+relu+quant over padded buffer (zeros the halo of a1 as side effect)
__global__ void act1_kernel(const float* __restrict__ g1,
                            const float* __restrict__ b1) {
    int idx = blockIdx.x * 256 + threadIdx.x;   // MPAD*256
    int mrow = idx >> 8, c = idx & 255;
    int rem = mrow % PSP;
    int hp = rem / PW, wp = rem - hp * PW;
    signed char out = 0;
    if ((hp >= 1) && (hp <= 56) && (wp >= 1) && (wp <= 56)) {
        float ys = __int_as_float(g_wmaxbits[0]) * (1.0f / 225.0f);
        float y  = (float)g_y0[idx] * ys;
        float xn = (y - g_mean1[c]) * g_rstd1[c] * g1[c] + b1[c];
        float r  = fminf(fmaxf(xn, 0.0f), 1.0f);
        out = (signed char)__float2int_rn(r * 15.0f);
    }
    g_a1[(size_t)(mrow + GUARD) * CCH + c] = out;
}

// out = y0*ys1 + x  (NHWC->NCHW transpose via smem tile)
__global__ void final_out_kernel(const float* __restrict__ x,
                                 float* __restrict__ out) {
    __shared__ float tile[32][33];
    int n = blockIdx.z, c0 = blockIdx.y * 32, hw0 = blockIdx.x * 32;
    int tx = threadIdx.x, ty = threadIdx.y;
    float ys = __int_as_float(g_wmaxbits[1]) * (1.0f / 225.0f);
#pragma unroll
    for (int i = 0; i < 4; i++) {
        int hw = hw0 + ty + 8 * i;
        int h = hw / 56, w = hw - h * 56;
        int mrow = n * PSP + (h + 1) * PW + (w + 1);
        tile[ty + 8 * i][tx] = (float)g_y0[(size_t)mrow * CCH + c0 + tx] * ys;
    }
    __syncthreads();
#pragma unroll
    for (int i = 0; i < 4; i++) {
        int c = c0 + ty + 8 * i;
        size_t o = ((size_t)(n * CCH + c)) * HWSZ + hw0 + tx;
        out[o] = tile[tx][ty + 8 * i] + x[o];
    }
}

// ---------------------------------------------------------------------------
extern "C" void kernel_launch(void* const* d_in, const int* in_sizes, int n_in,
                              void* d_out, int out_size) {
    const float* x  = (const float*)d_in[0];
    const float* g0 = (const float*)d_in[1];
    const float* b0 = (const float*)d_in[2];
    const float* w0 = (const float*)d_in[3];
    const float* g1 = (const float*)d_in[4];
    const float* b1 = (const float*)d_in[5];
    const float* w1 = (const float*)d_in[6];
    float* out = (float*)d_out;

    void *pa0, *pa1, *pw0, *pw1, *py0;
    cudaGetSymbolAddress(&pa0, g_a0);
    cudaGetSymbolAddress(&pa1, g_a1);
    cudaGetSymbolAddress(&pw0, g_wq0);
    cudaGetSymbolAddress(&pw1, g_wq1);
    cudaGetSymbolAddress(&py0, g_y0);

    cudaFuncSetAttribute(conv_imma_kernel,
                         cudaFuncAttributeMaxDynamicSharedMemorySize, 65536);

    init_kernel<<<1, 256>>>();
    wabsmax_kernel<<<256, 256>>>(w0, 0);
    wabsmax_kernel<<<256, 256>>>(w1, 1);
    wquant_kernel<<<(KW_ELEMS + 255) / 256, 256>>>(w0, 0);
    wquant_kernel<<<(KW_ELEMS + 255) / 256, 256>>>(w1, 1);
    bn0_stats_kernel<<<256, 256>>>(x);
    act0_kernel<<<dim3(98, 8, 16), dim3(32, 8)>>>(x, g0, b0);
    zero_halo0_kernel<<<MPAD, 256>>>();
    conv_imma_kernel<<<dim3(MTILES, 2), 256, 65536>>>(
        (const signed char*)pa0 + (size_t)GUARD * CCH,
        (const signed char*)pw0, (int*)py0);
    bn1_stats_kernel<<<256, 256>>>();
    bn1_final_kernel<<<1, 256>>>();
    act1_kernel<<<MPAD, 256>>>(g1, b1);
    conv_imma_kernel<<<dim3(MTILES, 2), 256, 65536>>>(
        (const signed char*)pa1 + (size_t)GUARD * CCH,
        (const signed char*)pw1, (int*)py0);
    final_out_kernel<<<dim3(98, 8, 16), dim3(32, 8)>>>(x, out);
}